// round 2
// baseline (speedup 1.0000x reference)
#include <cuda_runtime.h>
#include <math.h>

#define BB 4
#define NN 4096
#define DD 256
#define MTOT (BB*NN)   // 16384

// Scratch (static device allocations are the sanctioned mechanism)
__device__ float g_Q[MTOT*DD];
__device__ float g_K[MTOT*DD];
__device__ float g_V[MTOT*DD];
__device__ float g_att[MTOT*DD];

// ---------------------------------------------------------------------------
// GEMM: C[M,256] = A[M,256] @ W[256,256] (+ optional bias), 64x64 tile,
// 256 threads, 4x4 register tile per thread, BK=16.
// ---------------------------------------------------------------------------
template<bool ADD_BIAS>
__global__ __launch_bounds__(256) void gemm256(const float* __restrict__ A,
                                               const float* __restrict__ W,
                                               const float* __restrict__ bias,
                                               float* __restrict__ C)
{
    __shared__ float As[64][17];   // padded to avoid bank conflicts
    __shared__ float Ws[16][64];

    const int t  = threadIdx.x;
    const int tx = t & 15;
    const int ty = t >> 4;
    const int m0 = blockIdx.x * 64;
    const int n0 = blockIdx.y * 64;

    const int lr = t >> 2;          // As load row (0..63)
    const int lc = (t & 3) * 4;     // As load col (0,4,8,12)

    float acc[4][4] = {};

    for (int kk = 0; kk < 256; kk += 16) {
        float4 av = *(const float4*)(A + (size_t)(m0 + lr) * 256 + kk + lc);
        As[lr][lc + 0] = av.x; As[lr][lc + 1] = av.y;
        As[lr][lc + 2] = av.z; As[lr][lc + 3] = av.w;
        float4 wv = *(const float4*)(W + (size_t)(kk + ty) * 256 + n0 + tx * 4);
        *(float4*)&Ws[ty][tx * 4] = wv;
        __syncthreads();

        #pragma unroll
        for (int c = 0; c < 16; c++) {
            float a0 = As[ty*4+0][c];
            float a1 = As[ty*4+1][c];
            float a2 = As[ty*4+2][c];
            float a3 = As[ty*4+3][c];
            float4 w = *(const float4*)&Ws[c][tx * 4];
            acc[0][0] += a0*w.x; acc[0][1] += a0*w.y; acc[0][2] += a0*w.z; acc[0][3] += a0*w.w;
            acc[1][0] += a1*w.x; acc[1][1] += a1*w.y; acc[1][2] += a1*w.z; acc[1][3] += a1*w.w;
            acc[2][0] += a2*w.x; acc[2][1] += a2*w.y; acc[2][2] += a2*w.z; acc[2][3] += a2*w.w;
            acc[3][0] += a3*w.x; acc[3][1] += a3*w.y; acc[3][2] += a3*w.z; acc[3][3] += a3*w.w;
        }
        __syncthreads();
    }

    float4 bv = make_float4(0.f, 0.f, 0.f, 0.f);
    if (ADD_BIAS) bv = *(const float4*)(bias + n0 + tx * 4);
    #pragma unroll
    for (int j = 0; j < 4; j++) {
        float4 o = make_float4(acc[j][0] + bv.x, acc[j][1] + bv.y,
                               acc[j][2] + bv.z, acc[j][3] + bv.w);
        *(float4*)(C + (size_t)(m0 + ty*4 + j) * 256 + n0 + tx * 4) = o;
    }
}

// ---------------------------------------------------------------------------
// Attention: per q-row streaming (max, argmax, sumexp) over all 4096 keys,
// then out_row = p * V[argmax] if p >= 0.6 else 0. The attention matrix and
// attn@V GEMM are never materialized (softmax rows sum to 1, so at most one
// entry can be >= 0.6, and it must be the row max).
// ---------------------------------------------------------------------------
#define QPAD 260
#define KPAD 33
#define SMEM_ATTN ((size_t)(64*QPAD + 64*KPAD + 64) * sizeof(float) + 64 * sizeof(int))

__global__ __launch_bounds__(256) void attn_kernel(const float* __restrict__ Qg_,
                                                   const float* __restrict__ Kg_,
                                                   const float* __restrict__ Vg_,
                                                   float* __restrict__ Og_)
{
    extern __shared__ float sm[];
    float* Qs      = sm;                  // [64][QPAD]
    float* Ks      = Qs + 64 * QPAD;      // [64][KPAD]
    float* rowsum  = Ks + 64 * KPAD;      // [64]
    int*   rowarg  = (int*)(rowsum + 64); // [64]

    const int t  = threadIdx.x;
    const int tx = t & 15;
    const int ty = t >> 4;
    const int b  = blockIdx.y;
    const int q0 = blockIdx.x * 64;
    const float SCALE = 0.17677669529663689f;   // (256/8)^-0.5

    const float* Qg = Qg_ + (size_t)(b * NN + q0) * DD;
    const float* Kb = Kg_ + (size_t)b * NN * DD;

    // Load 64x256 Q tile (pre-scaled) into padded smem
    #pragma unroll
    for (int i = 0; i < 16; i++) {
        int f4 = t + i * 256;
        int r = f4 >> 6, c4 = f4 & 63;
        float4 v = *(const float4*)(Qg + r * DD + c4 * 4);
        float4 s = make_float4(v.x * SCALE, v.y * SCALE, v.z * SCALE, v.w * SCALE);
        *(float4*)&Qs[r * QPAD + c4 * 4] = s;
    }

    // Per-row online-softmax state (identical copies in all 16 lanes of a row group)
    float rm[4], rs[4];
    int   ra[4];
    #pragma unroll
    for (int j = 0; j < 4; j++) { rm[j] = -1e30f; rs[j] = 0.f; ra[j] = 0; }

    const int klr = t >> 2;
    const int klc = (t & 3) * 8;

    for (int mt = 0; mt < 64; mt++) {
        float acc[4][4] = {};
        const float* Kt = Kb + (size_t)(mt * 64) * DD;

        for (int kk = 0; kk < 256; kk += 32) {
            __syncthreads();   // protect Ks from readers of previous chunk
            {
                const float* src = Kt + (size_t)klr * DD + kk + klc;
                float4 v0 = *(const float4*)(src);
                float4 v1 = *(const float4*)(src + 4);
                float* dst = &Ks[klr * KPAD + klc];
                dst[0]=v0.x; dst[1]=v0.y; dst[2]=v0.z; dst[3]=v0.w;
                dst[4]=v1.x; dst[5]=v1.y; dst[6]=v1.z; dst[7]=v1.w;
            }
            __syncthreads();

            #pragma unroll
            for (int c = 0; c < 32; c++) {
                float a[4], bv[4];
                #pragma unroll
                for (int j = 0; j < 4; j++) a[j]  = Qs[(ty*4 + j) * QPAD + kk + c];
                #pragma unroll
                for (int i = 0; i < 4; i++) bv[i] = Ks[(tx*4 + i) * KPAD + c];
                #pragma unroll
                for (int j = 0; j < 4; j++)
                    #pragma unroll
                    for (int i = 0; i < 4; i++)
                        acc[j][i] += a[j] * bv[i];
            }
        }

        // Row reduction: each row's 64 scores live in 16 consecutive lanes
        #pragma unroll
        for (int j = 0; j < 4; j++) {
            float lm = acc[j][0];
            int   la = tx * 4;
            #pragma unroll
            for (int i = 1; i < 4; i++)
                if (acc[j][i] > lm) { lm = acc[j][i]; la = tx * 4 + i; }
            #pragma unroll
            for (int off = 8; off; off >>= 1) {
                float om = __shfl_xor_sync(0xffffffffu, lm, off);
                int   oa = __shfl_xor_sync(0xffffffffu, la, off);
                if (om > lm || (om == lm && oa < la)) { lm = om; la = oa; }
            }
            float ts = 0.f;
            #pragma unroll
            for (int i = 0; i < 4; i++) ts += __expf(acc[j][i] - lm);
            #pragma unroll
            for (int off = 8; off; off >>= 1)
                ts += __shfl_xor_sync(0xffffffffu, ts, off);

            if (lm > rm[j]) {
                rs[j] = rs[j] * __expf(rm[j] - lm) + ts;
                rm[j] = lm;
                ra[j] = mt * 64 + la;
            } else {
                rs[j] += ts * __expf(lm - rm[j]);
            }
        }
    }

    if (tx == 0) {
        #pragma unroll
        for (int j = 0; j < 4; j++) {
            rowsum[ty*4 + j] = rs[j];
            rowarg[ty*4 + j] = ra[j];
        }
    }
    __syncthreads();

    // Gather: out_row = p * V[argmax] if p >= 0.6 else 0
    const float* Vb = Vg_ + (size_t)b * NN * DD;
    float*       Og = Og_ + (size_t)(b * NN + q0) * DD;
    #pragma unroll
    for (int i = 0; i < 16; i++) {
        int f4 = t + i * 256;
        int r = f4 >> 6, c4 = f4 & 63;
        float p = 1.0f / rowsum[r];
        float4 o = make_float4(0.f, 0.f, 0.f, 0.f);
        if (p >= 0.6f) {
            float4 v = *(const float4*)(Vb + (size_t)rowarg[r] * DD + c4 * 4);
            o = make_float4(v.x * p, v.y * p, v.z * p, v.w * p);
        }
        *(float4*)(Og + r * DD + c4 * 4) = o;
    }
}

// ---------------------------------------------------------------------------
extern "C" void kernel_launch(void* const* d_in, const int* in_sizes, int n_in,
                              void* d_out, int out_size)
{
    const float* x  = (const float*)d_in[0];
    const float* y  = (const float*)d_in[1];
    const float* Wq = (const float*)d_in[2];
    const float* Wk = (const float*)d_in[3];
    const float* Wv = (const float*)d_in[4];
    const float* Wp = (const float*)d_in[5];
    const float* bp = (const float*)d_in[6];
    float* out = (float*)d_out;

    float *Q, *K, *V, *Att;
    cudaGetSymbolAddress((void**)&Q,   g_Q);
    cudaGetSymbolAddress((void**)&K,   g_K);
    cudaGetSymbolAddress((void**)&V,   g_V);
    cudaGetSymbolAddress((void**)&Att, g_att);

    cudaFuncSetAttribute(attn_kernel,
                         cudaFuncAttributeMaxDynamicSharedMemorySize,
                         (int)SMEM_ATTN);

    dim3 ggrid(MTOT / 64, DD / 64);
    gemm256<false><<<ggrid, 256>>>(x, Wq, nullptr, Q);
    gemm256<false><<<ggrid, 256>>>(y, Wk, nullptr, K);
    gemm256<false><<<ggrid, 256>>>(x, Wv, nullptr, V);

    attn_kernel<<<dim3(NN / 64, BB), 256, SMEM_ATTN>>>(Q, K, V, Att);

    gemm256<true><<<ggrid, 256>>>(Att, Wp, bp, out);
}

// round 6
// speedup vs baseline: 3.3747x; 3.3747x over previous
#include <cuda_runtime.h>
#include <cuda_fp16.h>
#include <math.h>
#include <stdint.h>

#define BB 4
#define NN 4096
#define DD 256
#define MTOT (BB*NN)          // 16384
#define KAUG 768              // 3 x 256 split-fp16 augmented K
#define SCALE_F 0.17677669529663689f

// ---------------- static device scratch ------------------------------------
__device__ __half g_Aaug[(size_t)MTOT*KAUG];   // xaug, later reused for att-aug
__device__ __half g_Baug[(size_t)MTOT*KAUG];   // yaug
__device__ __half g_Kaug[(size_t)MTOT*KAUG];   // K split (B-style)
__device__ float  g_Q [(size_t)MTOT*DD];
__device__ float  g_K [(size_t)MTOT*DD];
__device__ float  g_V [(size_t)MTOT*DD];
__device__ float  g_att[(size_t)MTOT*DD];
__device__ __half g_Wt[4][(size_t)DD*KAUG];    // weights transposed + split (B-style)

// ---------------- PTX helpers ----------------------------------------------
__device__ __forceinline__ uint32_t smem_u32(const void* p){
    uint32_t a;
    asm("{ .reg .u64 t; cvta.to.shared.u64 t, %1; cvt.u32.u64 %0, t; }" : "=r"(a) : "l"(p));
    return a;
}
#define CP16(dst, src) \
    asm volatile("cp.async.cg.shared.global [%0], [%1], 16;" :: "r"(dst), "l"(src) : "memory")
#define CPC()  asm volatile("cp.async.commit_group;" ::: "memory")
#define CPW0() asm volatile("cp.async.wait_group 0;" ::: "memory")

__device__ __forceinline__ void ldsm4(uint32_t a, uint32_t& r0, uint32_t& r1,
                                      uint32_t& r2, uint32_t& r3){
    asm volatile("ldmatrix.sync.aligned.m8n8.x4.shared.b16 {%0,%1,%2,%3}, [%4];"
        : "=r"(r0), "=r"(r1), "=r"(r2), "=r"(r3) : "r"(a));
}
__device__ __forceinline__ void mma16816(float* c,
        uint32_t a0, uint32_t a1, uint32_t a2, uint32_t a3,
        uint32_t b0, uint32_t b1){
    asm volatile("mma.sync.aligned.m16n8k16.row.col.f32.f16.f16.f32 "
        "{%0,%1,%2,%3}, {%4,%5,%6,%7}, {%8,%9}, {%0,%1,%2,%3};"
        : "+f"(c[0]), "+f"(c[1]), "+f"(c[2]), "+f"(c[3])
        : "r"(a0), "r"(a1), "r"(a2), "r"(a3), "r"(b0), "r"(b1));
}

// ---------------- prep kernels ----------------------------------------------
// STYLE 0 (A-side): [h | h | l]   STYLE 1 (B-side): [h | l | h]
template<int STYLE>
__global__ void prep_aug(const float* __restrict__ src, __half* __restrict__ dst)
{
    const size_t total = (size_t)MTOT * 64;   // float4 count
    for (size_t i = (size_t)blockIdx.x*blockDim.x + threadIdx.x; i < total;
         i += (size_t)gridDim.x*blockDim.x) {
        size_t row = i >> 6; int c4 = (int)(i & 63);
        float4 v = ((const float4*)src)[i];
        __half h0=__float2half_rn(v.x), h1=__float2half_rn(v.y);
        __half h2=__float2half_rn(v.z), h3=__float2half_rn(v.w);
        __half l0=__float2half_rn(v.x-__half2float(h0));
        __half l1=__float2half_rn(v.y-__half2float(h1));
        __half l2=__float2half_rn(v.z-__half2float(h2));
        __half l3=__float2half_rn(v.w-__half2float(h3));
        __half2 H01=__halves2half2(h0,h1), H23=__halves2half2(h2,h3);
        __half2 L01=__halves2half2(l0,l1), L23=__halves2half2(l2,l3);
        __half* base = dst + row*KAUG + c4*4;
        ((__half2*)base)[0] = H01; ((__half2*)base)[1] = H23;
        __half2* d1 = (__half2*)(base + 256);
        __half2* d2 = (__half2*)(base + 512);
        if (STYLE == 0) { d1[0]=H01; d1[1]=H23; d2[0]=L01; d2[1]=L23; }
        else            { d1[0]=L01; d1[1]=L23; d2[0]=H01; d2[1]=H23; }
    }
}

// W [256k x 256n] fp32 -> Wt [256n x 768k] half, B-style split, transposed
__global__ void prep_wt(const float* __restrict__ W, __half* __restrict__ Wt)
{
    int k = blockIdx.x;
    int n = threadIdx.x;
    float v = W[(size_t)k*DD + n];
    __half h = __float2half_rn(v);
    __half l = __float2half_rn(v - __half2float(h));
    Wt[(size_t)n*KAUG + k]       = h;
    Wt[(size_t)n*KAUG + 256 + k] = l;
    Wt[(size_t)n*KAUG + 512 + k] = h;
}

// ---------------- HMMA GEMM: C[M,256] = Aaug[M,768] . Wt[256,768]^T (+bias) --
template<bool BIAS>
__global__ __launch_bounds__(256) void hgemm(const __half* __restrict__ A,
                                             const __half* __restrict__ Bw,
                                             const float* __restrict__ bias,
                                             float* __restrict__ C)
{
    __shared__ __align__(16) char sm[4*10240];   // A[2][128x80B], B[2][128x80B]
    const uint32_t sb = smem_u32(sm);
    const int t = threadIdx.x, lane = t & 31, wid = t >> 5;
    const int wm = wid >> 1, wn = wid & 1;
    const int m0 = blockIdx.x * 128, n0 = blockIdx.y * 128;

    float c[2][8][4] = {};

    // prologue: chunk 0 -> buf 0
    {
        #pragma unroll
        for (int i = 0; i < 2; i++) {
            int sidx = t*2 + i; int row = sidx >> 2, seg = sidx & 3;
            CP16(sb + row*80 + seg*16,           A  + (size_t)(m0+row)*KAUG + seg*8);
            CP16(sb + 20480 + row*80 + seg*16,   Bw + (size_t)(n0+row)*KAUG + seg*8);
        }
        CPC();
    }

    const uint32_t aRowOff = (uint32_t)(wm*32 + (lane&15))*80 + ((lane>>4)&1)*16;
    const uint32_t bRowOff = (uint32_t)(wn*64 + (lane&7) + ((lane>>3)&1)*8)*80
                           + ((lane>>4)&1)*16;

    for (int ch = 0; ch < 24; ch++) {
        int buf = ch & 1;
        CPW0();
        __syncthreads();
        if (ch + 1 < 24) {
            int nb = buf ^ 1;
            #pragma unroll
            for (int i = 0; i < 2; i++) {
                int sidx = t*2 + i; int row = sidx >> 2, seg = sidx & 3;
                CP16(sb + nb*10240 + row*80 + seg*16,
                     A  + (size_t)(m0+row)*KAUG + (ch+1)*32 + seg*8);
                CP16(sb + 20480 + nb*10240 + row*80 + seg*16,
                     Bw + (size_t)(n0+row)*KAUG + (ch+1)*32 + seg*8);
            }
            CPC();
        }
        uint32_t aBase = sb + buf*10240 + aRowOff;
        uint32_t bBase = sb + 20480 + buf*10240 + bRowOff;
        #pragma unroll
        for (int ks = 0; ks < 2; ks++) {
            uint32_t a0,a1,a2,a3,a4,a5,a6,a7;
            ldsm4(aBase + ks*32,            a0,a1,a2,a3);
            ldsm4(aBase + 16*80 + ks*32,    a4,a5,a6,a7);
            #pragma unroll
            for (int p = 0; p < 4; p++) {
                uint32_t b0,b1,b2,b3;
                ldsm4(bBase + p*1280 + ks*32, b0,b1,b2,b3);
                mma16816(c[0][2*p+0], a0,a1,a2,a3, b0,b2);
                mma16816(c[0][2*p+1], a0,a1,a2,a3, b1,b3);
                mma16816(c[1][2*p+0], a4,a5,a6,a7, b0,b2);
                mma16816(c[1][2*p+1], a4,a5,a6,a7, b1,b3);
            }
        }
    }

    #pragma unroll
    for (int mi = 0; mi < 2; mi++)
        #pragma unroll
        for (int ni = 0; ni < 8; ni++) {
            int row = m0 + wm*32 + mi*16 + (lane>>2);
            int col = n0 + wn*64 + ni*8 + 2*(lane&3);
            float b0v = 0.f, b1v = 0.f;
            if (BIAS) { b0v = bias[col]; b1v = bias[col+1]; }
            *(float2*)(C + (size_t)row*DD + col) =
                make_float2(c[mi][ni][0]+b0v, c[mi][ni][1]+b1v);
            *(float2*)(C + (size_t)(row+8)*DD + col) =
                make_float2(c[mi][ni][2]+b0v, c[mi][ni][3]+b1v);
        }
}

// ---------------- HMMA attention --------------------------------------------
#define QS_BYTES   (128*1552)              // Q aug tile, row stride 1552B
#define AKB_OFF    QS_BYTES
#define AKS_BYTES  (128*80)                // one K chunk buffer
#define MRG_OFF    (AKB_OFF + 2*AKS_BYTES) // 219136
#define SMEM_ATTN  (MRG_OFF + 3*1024)      // 222208

__global__ __launch_bounds__(256) void attn_tc(const float* __restrict__ Qg_,
        const __half* __restrict__ Kaug_, const float* __restrict__ Vg_,
        float* __restrict__ Og_)
{
    extern __shared__ __align__(128) char smem[];
    const uint32_t sb = smem_u32(smem);
    const int t = threadIdx.x, lane = t & 31, wid = t >> 5;
    const int wm = wid >> 1, wn = wid & 1;
    const int b = blockIdx.y, q0 = blockIdx.x * 128;

    const __half* Kb = Kaug_ + (size_t)b*NN*KAUG;

    // prologue prefetch: key-tile 0, chunk 0 -> buf 0 (overlaps Q build)
    {
        #pragma unroll
        for (int i = 0; i < 2; i++) {
            int sidx = t*2 + i; int row = sidx >> 2, seg = sidx & 3;
            CP16(sb + AKB_OFF + row*80 + seg*16, Kb + (size_t)row*KAUG + seg*8);
        }
        CPC();
    }

    // build Q aug tile ([h|h|l], pre-scaled) in smem
    const float* Qg = Qg_ + (size_t)(b*NN + q0)*DD;
    #pragma unroll 4
    for (int i = 0; i < 32; i++) {
        int e4 = t + i*256;
        int row = e4 >> 6, c4 = e4 & 63;
        float4 v = ((const float4*)Qg)[(size_t)row*64 + c4];
        v.x *= SCALE_F; v.y *= SCALE_F; v.z *= SCALE_F; v.w *= SCALE_F;
        __half h0=__float2half_rn(v.x), h1=__float2half_rn(v.y);
        __half h2=__float2half_rn(v.z), h3=__float2half_rn(v.w);
        __half2 H01=__halves2half2(h0,h1), H23=__halves2half2(h2,h3);
        __half2 L01=__halves2half2(__float2half_rn(v.x-__half2float(h0)),
                                   __float2half_rn(v.y-__half2float(h1)));
        __half2 L23=__halves2half2(__float2half_rn(v.z-__half2float(h2)),
                                   __float2half_rn(v.w-__half2float(h3)));
        char* base = smem + (size_t)row*1552 + (size_t)c4*8;
        *(__half2*)(base)        = H01; *(__half2*)(base+4)    = H23;
        *(__half2*)(base+512)    = H01; *(__half2*)(base+516)  = H23;
        *(__half2*)(base+1024)   = L01; *(__half2*)(base+1028) = L23;
    }

    float c[2][8][4] = {};
    float rm[4], rs[4]; int ra[4];
    #pragma unroll
    for (int j = 0; j < 4; j++) { rm[j] = -3.0e38f; rs[j] = 0.f; ra[j] = 0; }

    const uint32_t aRowOff = (uint32_t)(wm*32 + (lane&15))*1552 + ((lane>>4)&1)*16;
    const uint32_t bRowOff = (uint32_t)(wn*64 + (lane&7) + ((lane>>3)&1)*8)*80
                           + ((lane>>4)&1)*16;

    for (int kt = 0; kt < 32; kt++) {
        for (int ch = 0; ch < 24; ch++) {
            int glob = kt*24 + ch;
            int buf = glob & 1;
            CPW0();
            __syncthreads();
            if (glob + 1 < 768) {
                int nx = glob + 1;
                int nkt = nx / 24, nch = nx % 24, nb = buf ^ 1;
                #pragma unroll
                for (int i = 0; i < 2; i++) {
                    int sidx = t*2 + i; int row = sidx >> 2, seg = sidx & 3;
                    CP16(sb + AKB_OFF + nb*AKS_BYTES + row*80 + seg*16,
                         Kb + (size_t)(nkt*128+row)*KAUG + nch*32 + seg*8);
                }
                CPC();
            }
            uint32_t aBase = sb + aRowOff + (uint32_t)ch*64;
            uint32_t bBase = sb + AKB_OFF + buf*AKS_BYTES + bRowOff;
            #pragma unroll
            for (int ks = 0; ks < 2; ks++) {
                uint32_t a0,a1,a2,a3,a4,a5,a6,a7;
                ldsm4(aBase + ks*32,             a0,a1,a2,a3);
                ldsm4(aBase + 16*1552 + ks*32,   a4,a5,a6,a7);
                #pragma unroll
                for (int p = 0; p < 4; p++) {
                    uint32_t b0,b1,b2,b3;
                    ldsm4(bBase + p*1280 + ks*32, b0,b1,b2,b3);
                    mma16816(c[0][2*p+0], a0,a1,a2,a3, b0,b2);
                    mma16816(c[0][2*p+1], a0,a1,a2,a3, b1,b3);
                    mma16816(c[1][2*p+0], a4,a5,a6,a7, b0,b2);
                    mma16816(c[1][2*p+1], a4,a5,a6,a7, b1,b3);
                }
            }
        }

        // ---- per-key-tile reduction: 128x128 scores live in c[][][] ----
        #pragma unroll
        for (int j = 0; j < 4; j++) {
            int mi = j >> 1, hr = (j & 1) * 2;
            float tm = -3.0e38f; int ta = 0;
            #pragma unroll
            for (int ni = 0; ni < 8; ni++) {
                float v0 = c[mi][ni][hr], v1 = c[mi][ni][hr+1];
                int col = ni*8 + 2*(lane&3);
                if (v0 > tm) { tm = v0; ta = col; }
                if (v1 > tm) { tm = v1; ta = col+1; }
            }
            #pragma unroll
            for (int off = 1; off <= 2; off <<= 1) {
                float om = __shfl_xor_sync(0xffffffffu, tm, off);
                int   oa = __shfl_xor_sync(0xffffffffu, ta, off);
                if (om > tm || (om == tm && oa < ta)) { tm = om; ta = oa; }
            }
            float ts = 0.f;
            #pragma unroll
            for (int ni = 0; ni < 8; ni++) {
                ts += __expf(c[mi][ni][hr]   - tm);
                ts += __expf(c[mi][ni][hr+1] - tm);
            }
            #pragma unroll
            for (int off = 1; off <= 2; off <<= 1)
                ts += __shfl_xor_sync(0xffffffffu, ts, off);
            if (tm > rm[j]) {
                rs[j] = rs[j]*__expf(rm[j]-tm) + ts;
                rm[j] = tm;
                ra[j] = kt*128 + wn*64 + ta;
            } else {
                rs[j] += ts*__expf(tm - rm[j]);
            }
        }
        #pragma unroll
        for (int mi = 0; mi < 2; mi++)
            #pragma unroll
            for (int ni = 0; ni < 8; ni++)
                #pragma unroll
                for (int r = 0; r < 4; r++) c[mi][ni][r] = 0.f;
    }

    // ---- merge the two n-halves per row, compute p and arg ----
    float* m_arr = (float*)(smem + MRG_OFF);
    float* s_arr = (float*)(smem + MRG_OFF + 1024);
    int*   a_arr = (int*)  (smem + MRG_OFF + 2048);
    if ((lane & 3) == 0) {
        #pragma unroll
        for (int j = 0; j < 4; j++) {
            int row = wm*32 + (j>>1)*16 + (j&1)*8 + (lane>>2);
            m_arr[wn*128 + row] = rm[j];
            s_arr[wn*128 + row] = rs[j];
            a_arr[wn*128 + row] = ra[j];
        }
    }
    __syncthreads();
    if (t < 128) {
        float m0v = m_arr[t], m1v = m_arr[128+t];
        float s0  = s_arr[t], s1  = s_arr[128+t];
        float mm  = fmaxf(m0v, m1v);
        float ss  = s0*__expf(m0v-mm) + s1*__expf(m1v-mm);
        int   aa  = (m0v >= m1v) ? a_arr[t] : a_arr[128+t];
        m_arr[t] = 1.0f / ss;
        a_arr[t] = aa;
    }
    __syncthreads();

    // ---- gather epilogue: out_row = p * V[arg] if p >= 0.6 else 0 ----
    const float* Vb = Vg_ + (size_t)b*NN*DD;
    float*       Og = Og_ + (size_t)(b*NN + q0)*DD;
    #pragma unroll 4
    for (int i = 0; i < 32; i++) {
        int e4 = t + i*256;
        int row = e4 >> 6, c4 = e4 & 63;
        float p = m_arr[row];
        float4 o = make_float4(0.f, 0.f, 0.f, 0.f);
        if (p >= 0.6f) {
            int a = a_arr[row];
            float4 v = ((const float4*)(Vb + (size_t)a*DD))[c4];
            o = make_float4(v.x*p, v.y*p, v.z*p, v.w*p);
        }
        ((float4*)Og)[(size_t)row*64 + c4] = o;
    }
}

// ---------------------------------------------------------------------------
extern "C" void kernel_launch(void* const* d_in, const int* in_sizes, int n_in,
                              void* d_out, int out_size)
{
    const float* x  = (const float*)d_in[0];
    const float* y  = (const float*)d_in[1];
    const float* Wq = (const float*)d_in[2];
    const float* Wk = (const float*)d_in[3];
    const float* Wv = (const float*)d_in[4];
    const float* Wp = (const float*)d_in[5];
    const float* bp = (const float*)d_in[6];
    float* out = (float*)d_out;

    __half *Aaug, *Baug, *Kaug, *Wt;
    float *Q, *K, *V, *Att;
    cudaGetSymbolAddress((void**)&Aaug, g_Aaug);
    cudaGetSymbolAddress((void**)&Baug, g_Baug);
    cudaGetSymbolAddress((void**)&Kaug, g_Kaug);
    cudaGetSymbolAddress((void**)&Q,    g_Q);
    cudaGetSymbolAddress((void**)&K,    g_K);
    cudaGetSymbolAddress((void**)&V,    g_V);
    cudaGetSymbolAddress((void**)&Att,  g_att);
    cudaGetSymbolAddress((void**)&Wt,   g_Wt);
    __half* WtQ = Wt;
    __half* WtK = Wt + (size_t)DD*KAUG;
    __half* WtV = Wt + (size_t)2*DD*KAUG;
    __half* WtP = Wt + (size_t)3*DD*KAUG;

    cudaFuncSetAttribute(attn_tc,
                         cudaFuncAttributeMaxDynamicSharedMemorySize, SMEM_ATTN);

    prep_wt<<<256, 256>>>(Wq, WtQ);
    prep_wt<<<256, 256>>>(Wk, WtK);
    prep_wt<<<256, 256>>>(Wv, WtV);
    prep_wt<<<256, 256>>>(Wp, WtP);
    prep_aug<0><<<2048, 256>>>(x, Aaug);
    prep_aug<0><<<2048, 256>>>(y, Baug);

    dim3 gg(MTOT/128, DD/128);
    hgemm<false><<<gg, 256>>>(Aaug, WtQ, nullptr, Q);
    hgemm<false><<<gg, 256>>>(Baug, WtK, nullptr, K);
    hgemm<false><<<gg, 256>>>(Aaug, WtV, nullptr, V);

    prep_aug<1><<<2048, 256>>>(K, Kaug);

    attn_tc<<<dim3(NN/128, BB), 256, SMEM_ATTN>>>(Q, Kaug, V, Att);

    prep_aug<0><<<2048, 256>>>(Att, Aaug);
    hgemm<true><<<gg, 256>>>(Aaug, WtP, bp, out);
}